// round 14
// baseline (speedup 1.0000x reference)
#include <cuda_runtime.h>
#include <cuda_fp16.h>
#include <cstdint>

#define N_NODES 100000
#define N_FEAT  512
#define N_EDGES 3200000
#define NCH16   (N_FEAT / 8)   // 64 uint4 (8-half) chunks per row

// Scratch (allocation-free rule: __device__ globals)
__device__ __half g_wh[(size_t)N_FEAT * N_FEAT];   // W in fp16
__device__ __half g_xw[(size_t)N_NODES * N_FEAT];  // X @ W in fp16
__device__ float g_dinv[N_NODES];                  // rsqrt(deg+1)
__device__ int   g_deg[N_NODES];                   // in-degree (no self loop)
__device__ int   g_off[N_NODES];                   // CSR chunk start
__device__ int   g_cursor[N_NODES];                // fill cursor
__device__ int2  g_csr[N_EDGES];                   // {src, norm-bits} grouped by dst
__device__ int   g_total;                          // chunk allocator

// ---------------------------------------------------------------------------
// fp32 -> fp16 helpers
// ---------------------------------------------------------------------------
__device__ __forceinline__ uint4 cvt8(const float4 a, const float4 b) {
    __half2 h0 = __floats2half2_rn(a.x, a.y);
    __half2 h1 = __floats2half2_rn(a.z, a.w);
    __half2 h2 = __floats2half2_rn(b.x, b.y);
    __half2 h3 = __floats2half2_rn(b.z, b.w);
    uint4 v;
    v.x = *reinterpret_cast<unsigned*>(&h0);
    v.y = *reinterpret_cast<unsigned*>(&h1);
    v.z = *reinterpret_cast<unsigned*>(&h2);
    v.w = *reinterpret_cast<unsigned*>(&h3);
    return v;
}

__global__ void cvtW_kernel(const float* __restrict__ W) {
    int i = blockIdx.x * blockDim.x + threadIdx.x;   // over 512*512/8
    if (i < N_FEAT * N_FEAT / 8) {
        const float4* s = reinterpret_cast<const float4*>(W) + 2 * (size_t)i;
        reinterpret_cast<uint4*>(g_wh)[i] = cvt8(s[0], s[1]);
    }
}

// ---------------------------------------------------------------------------
// CSR build
// ---------------------------------------------------------------------------
__global__ void zero_kernel() {
    int i = blockIdx.x * blockDim.x + threadIdx.x;
    if (i < N_NODES) g_deg[i] = 0;
    if (i == 0) g_total = 0;
}

__global__ void count_deg_kernel(const int* __restrict__ dst) {
    int e = blockIdx.x * blockDim.x + threadIdx.x;
    if (e < N_EDGES) atomicAdd(&g_deg[__ldcs(dst + e)], 1);
}

__global__ void alloc_kernel() {
    int i = blockIdx.x * blockDim.x + threadIdx.x;
    if (i < N_NODES) {
        int d = g_deg[i];
        int o = atomicAdd(&g_total, d);   // disjoint contiguous ranges
        g_off[i] = o;
        g_cursor[i] = o;
        g_dinv[i] = rsqrtf((float)d + 1.0f);  // +1 = self loop
    }
}

__global__ void fill_kernel(const int* __restrict__ ei) {
    int e = blockIdx.x * blockDim.x + threadIdx.x;
    if (e < N_EDGES) {
        int s = __ldcs(ei + e);
        int d = __ldcs(ei + N_EDGES + e);
        int pos = atomicAdd(&g_cursor[d], 1);
        float nm = g_dinv[s] * g_dinv[d];   // dinv ready (fill after alloc)
        g_csr[pos] = make_int2(s, __float_as_int(nm));
    }
}

// ---------------------------------------------------------------------------
// GEMM: g_xw = fp16(onehot @ g_wh), fp16 mma m16n8k16 with fp32 accumulate.
// Launched 4x (pass = column quarter) to pipeline with aggregation.
// 256x128x32 block tile, 256 threads = 8 warps (4m x 2n), warp tile 64x64.
// ---------------------------------------------------------------------------
#define BM 256
#define BN 128
#define BK 32
#define SAH 40    // A smem row stride (halves)
#define SBH 136   // B smem row stride (halves)
#define A_BUF_H (BM * SAH)              // 10240 halves per buffer
#define B_BASE_H (2 * A_BUF_H)          // 20480
#define B_BUF_H (BK * SBH)              // 4352 halves per buffer
#define SMEM_DYN ((B_BASE_H + 2 * B_BUF_H) * 2)  // 58368 bytes

__device__ __forceinline__ unsigned smem_u32(const void* p) {
    return (unsigned)__cvta_generic_to_shared(p);
}

__device__ __forceinline__ void ldsm_x4(unsigned* r, const void* p) {
    asm volatile("ldmatrix.sync.aligned.m8n8.x4.shared.b16 {%0,%1,%2,%3}, [%4];"
                 : "=r"(r[0]), "=r"(r[1]), "=r"(r[2]), "=r"(r[3]) : "r"(smem_u32(p)));
}

__device__ __forceinline__ void ldsm_x4_trans(unsigned* r, const void* p) {
    asm volatile("ldmatrix.sync.aligned.m8n8.x4.trans.shared.b16 {%0,%1,%2,%3}, [%4];"
                 : "=r"(r[0]), "=r"(r[1]), "=r"(r[2]), "=r"(r[3]) : "r"(smem_u32(p)));
}

__device__ __forceinline__ void mma_f16(float* c, const unsigned* a, const unsigned* b) {
    asm volatile(
        "mma.sync.aligned.m16n8k16.row.col.f32.f16.f16.f32 "
        "{%0,%1,%2,%3}, {%4,%5,%6,%7}, {%8,%9}, {%0,%1,%2,%3};"
        : "+f"(c[0]), "+f"(c[1]), "+f"(c[2]), "+f"(c[3])
        : "r"(a[0]), "r"(a[1]), "r"(a[2]), "r"(a[3]), "r"(b[0]), "r"(b[1]));
}

__global__ __launch_bounds__(256, 1) void gemm_kernel(const float* __restrict__ A, int pass) {
    extern __shared__ __half sm[];

    const int tid = threadIdx.x;
    const int rowBase = blockIdx.y * BM;
    const int colBase = pass * BN;

    const int arow = tid >> 2;            // 0..63 (+64*i)
    const int akc  = (tid & 3) * 8;       // 0,8,16,24
    const int bk   = tid >> 4;            // 0..15 (+16*j)
    const int bn   = (tid & 15) * 8;      // 0..120

    const float*  Aptr = A + (size_t)(rowBase + arow) * N_FEAT + akc;
    const __half* Bptr = g_wh + (size_t)bk * N_FEAT + colBase + bn;

    bool aok[4];
#pragma unroll
    for (int i = 0; i < 4; i++) aok[i] = (rowBase + arow + 64 * i) < N_NODES;

    const int warpId = tid >> 5;
    const int lane = tid & 31;
    const int wm = (warpId >> 1) * 64;    // 0,64,128,192
    const int wn = (warpId & 1) * 64;     // 0,64
    const int lr = lane & 15;             // ldmatrix row
    const int lc = (lane >> 4) * 8;       // ldmatrix col block
    const int qr = lane >> 2;             // mma c row
    const int qc = lane & 3;              // mma c col pair

    float acc[4][8][4] = {};              // [mi][ni][reg]

    float4 aR[4][2];
    uint4 bR[2];
#pragma unroll
    for (int i = 0; i < 4; i++) {
        if (aok[i]) {
            aR[i][0] = __ldcs(reinterpret_cast<const float4*>(Aptr + (size_t)64 * i * N_FEAT));
            aR[i][1] = __ldcs(reinterpret_cast<const float4*>(Aptr + (size_t)64 * i * N_FEAT + 4));
        } else {
            aR[i][0] = aR[i][1] = make_float4(0.f, 0.f, 0.f, 0.f);
        }
    }
#pragma unroll
    for (int j = 0; j < 2; j++)
        bR[j] = *reinterpret_cast<const uint4*>(Bptr + (size_t)16 * j * N_FEAT);

    int buf = 0;
    for (int kb = 0; kb < N_FEAT; kb += BK) {
#pragma unroll
        for (int i = 0; i < 4; i++)
            *reinterpret_cast<uint4*>(&sm[buf * A_BUF_H + (arow + 64 * i) * SAH + akc]) =
                cvt8(aR[i][0], aR[i][1]);
#pragma unroll
        for (int j = 0; j < 2; j++)
            *reinterpret_cast<uint4*>(&sm[B_BASE_H + buf * B_BUF_H + (bk + 16 * j) * SBH + bn]) = bR[j];
        __syncthreads();

        if (kb + BK < N_FEAT) {
#pragma unroll
            for (int i = 0; i < 4; i++)
                if (aok[i]) {
                    aR[i][0] = __ldcs(reinterpret_cast<const float4*>(
                        Aptr + (size_t)64 * i * N_FEAT + kb + BK));
                    aR[i][1] = __ldcs(reinterpret_cast<const float4*>(
                        Aptr + (size_t)64 * i * N_FEAT + kb + BK + 4));
                }
#pragma unroll
            for (int j = 0; j < 2; j++)
                bR[j] = *reinterpret_cast<const uint4*>(
                    Bptr + (size_t)(kb + BK + 16 * j) * N_FEAT);
        }

#pragma unroll
        for (int ks = 0; ks < 2; ks++) {
            const int k0 = ks * 16;
            unsigned af[4][4];
#pragma unroll
            for (int mi = 0; mi < 4; mi++)
                ldsm_x4(af[mi], &sm[buf * A_BUF_H + (wm + mi * 16 + lr) * SAH + k0 + lc]);
            unsigned bf[4][4];
#pragma unroll
            for (int nj = 0; nj < 4; nj++)
                ldsm_x4_trans(bf[nj], &sm[B_BASE_H + buf * B_BUF_H + (k0 + lr) * SBH + wn + nj * 16 + lc]);
#pragma unroll
            for (int mi = 0; mi < 4; mi++)
#pragma unroll
                for (int ni = 0; ni < 8; ni++)
                    mma_f16(acc[mi][ni], af[mi], &bf[ni >> 1][(ni & 1) * 2]);
        }
        __syncthreads();
        buf ^= 1;
    }

#pragma unroll
    for (int mi = 0; mi < 4; mi++) {
        const int r0 = rowBase + wm + mi * 16 + qr;
        const int r1 = r0 + 8;
#pragma unroll
        for (int ni = 0; ni < 8; ni++) {
            const int col = colBase + wn + ni * 8 + 2 * qc;
            if (r0 < N_NODES) {
                __half2 h = __floats2half2_rn(acc[mi][ni][0], acc[mi][ni][1]);
                *reinterpret_cast<__half2*>(&g_xw[(size_t)r0 * N_FEAT + col]) = h;
            }
            if (r1 < N_NODES) {
                __half2 h = __floats2half2_rn(acc[mi][ni][2], acc[mi][ni][3]);
                *reinterpret_cast<__half2*>(&g_xw[(size_t)r1 * N_FEAT + col]) = h;
            }
        }
    }
}

// ---------------------------------------------------------------------------
// Aggregate one 128-column QUARTER. One warp per node; the two half-warps
// process two edges per iteration (16 lanes x 16B = 256B per edge), combined
// at the end via shfl_xor(16). Working set per quarter = 25.6 MB (L2-hot).
// ---------------------------------------------------------------------------
__device__ __forceinline__ void acc_half8(float4& a0, float4& a1, uint4 raw, float m) {
    __half2 h0 = *reinterpret_cast<__half2*>(&raw.x);
    __half2 h1 = *reinterpret_cast<__half2*>(&raw.y);
    __half2 h2 = *reinterpret_cast<__half2*>(&raw.z);
    __half2 h3 = *reinterpret_cast<__half2*>(&raw.w);
    float2 f0 = __half22float2(h0);
    float2 f1 = __half22float2(h1);
    float2 f2 = __half22float2(h2);
    float2 f3 = __half22float2(h3);
    a0.x = fmaf(f0.x, m, a0.x); a0.y = fmaf(f0.y, m, a0.y);
    a0.z = fmaf(f1.x, m, a0.z); a0.w = fmaf(f1.y, m, a0.w);
    a1.x = fmaf(f2.x, m, a1.x); a1.y = fmaf(f2.y, m, a1.y);
    a1.z = fmaf(f3.x, m, a1.z); a1.w = fmaf(f3.y, m, a1.w);
}

// Gather quarter q for node n. On return all 32 lanes hold the combined,
// bias-added, relu'd accumulators for uint4-chunk (q*16 + (lane&15)).
__device__ __forceinline__ void gather_quarter(int n, int q, int lane,
                                               float4& A0, float4& A1,
                                               const float* __restrict__ bias) {
    const int hw = lane >> 4;           // half-warp id: which edge of the pair
    const int c = lane & 15;
    const int chunk = q * 16 + c;
    const float dn = g_dinv[n];
    const uint4* __restrict__ xw4 = reinterpret_cast<const uint4*>(g_xw);

    A0 = make_float4(0.f, 0.f, 0.f, 0.f); A1 = A0;
    if (hw == 0)   // self loop counted once
        acc_half8(A0, A1, __ldcg(xw4 + (size_t)n * NCH16 + chunk), dn * dn);

    const int start = g_off[n];
    const int cnt = g_deg[n];
    const int2* __restrict__ lst = g_csr + start;

    int i = 0;
    for (; i + 8 <= cnt; i += 8) {      // 4 pairs = 8 edges per iter
        int2 e0 = __ldcs(lst + i + hw);
        int2 e1 = __ldcs(lst + i + 2 + hw);
        int2 e2 = __ldcs(lst + i + 4 + hw);
        int2 e3 = __ldcs(lst + i + 6 + hw);
        uint4 v0 = __ldcg(xw4 + (size_t)e0.x * NCH16 + chunk);
        uint4 v1 = __ldcg(xw4 + (size_t)e1.x * NCH16 + chunk);
        uint4 v2 = __ldcg(xw4 + (size_t)e2.x * NCH16 + chunk);
        uint4 v3 = __ldcg(xw4 + (size_t)e3.x * NCH16 + chunk);
        acc_half8(A0, A1, v0, __int_as_float(e0.y));
        acc_half8(A0, A1, v1, __int_as_float(e1.y));
        acc_half8(A0, A1, v2, __int_as_float(e2.y));
        acc_half8(A0, A1, v3, __int_as_float(e3.y));
    }
    for (; i + 2 <= cnt; i += 2) {
        int2 e = __ldcs(lst + i + hw);
        acc_half8(A0, A1, __ldcg(xw4 + (size_t)e.x * NCH16 + chunk), __int_as_float(e.y));
    }
    if (i < cnt && hw == 0) {           // odd tail edge
        int2 e = __ldcs(lst + i);
        acc_half8(A0, A1, __ldcg(xw4 + (size_t)e.x * NCH16 + chunk), __int_as_float(e.y));
    }

    // combine the two half-warps (lane i <-> lane i+16 hold the same chunk)
    A0.x += __shfl_xor_sync(0xFFFFFFFF, A0.x, 16);
    A0.y += __shfl_xor_sync(0xFFFFFFFF, A0.y, 16);
    A0.z += __shfl_xor_sync(0xFFFFFFFF, A0.z, 16);
    A0.w += __shfl_xor_sync(0xFFFFFFFF, A0.w, 16);
    A1.x += __shfl_xor_sync(0xFFFFFFFF, A1.x, 16);
    A1.y += __shfl_xor_sync(0xFFFFFFFF, A1.y, 16);
    A1.z += __shfl_xor_sync(0xFFFFFFFF, A1.z, 16);
    A1.w += __shfl_xor_sync(0xFFFFFFFF, A1.w, 16);

    // bias + relu (all lanes, duplicated across half-warps; harmless)
    const float4* b4 = reinterpret_cast<const float4*>(bias);
    float4 ba0 = b4[2 * chunk], ba1 = b4[2 * chunk + 1];
    A0.x = fmaxf(A0.x + ba0.x, 0.f); A0.y = fmaxf(A0.y + ba0.y, 0.f);
    A0.z = fmaxf(A0.z + ba0.z, 0.f); A0.w = fmaxf(A0.w + ba0.w, 0.f);
    A1.x = fmaxf(A1.x + ba1.x, 0.f); A1.y = fmaxf(A1.y + ba1.y, 0.f);
    A1.z = fmaxf(A1.z + ba1.z, 0.f); A1.w = fmaxf(A1.w + ba1.w, 0.f);
}

// Quarters 0..2: write relu'd logits.
__global__ __launch_bounds__(256) void aggregate_q_kernel(const float* __restrict__ bias,
                                                          float* __restrict__ out, int q) {
    const int n = blockIdx.x * 8 + (threadIdx.x >> 5);
    if (n >= N_NODES) return;
    const int lane = threadIdx.x & 31;
    float4 A0, A1;
    gather_quarter(n, q, lane, A0, A1, bias);
    const int hw = lane >> 4, c = lane & 15;
    float4* orow = reinterpret_cast<float4*>(out) + (size_t)n * (N_FEAT / 4);
    __stcs(orow + q * 32 + 2 * c + hw, hw ? A1 : A0);   // coalesced 1KB per warp
}

// Quarter 3 + fused softmax: re-read quarters 0..2, normalize the full row.
__global__ __launch_bounds__(256) void aggregate_q3_final_kernel(const float* __restrict__ bias,
                                                                 float* __restrict__ out) {
    const int n = blockIdx.x * 8 + (threadIdx.x >> 5);
    if (n >= N_NODES) return;
    const int lane = threadIdx.x & 31;
    const int hw = lane >> 4, c = lane & 15;
    float4 A0, A1;
    gather_quarter(n, 3, lane, A0, A1, bias);

    float4* orow = reinterpret_cast<float4*>(out) + (size_t)n * (N_FEAT / 4);
    float4 L[3];
#pragma unroll
    for (int t = 0; t < 3; t++) L[t] = __ldcg(orow + lane + 32 * t);

    // row max (relu output >= 0, so 0 is a valid floor; acc duplication is
    // harmless for max)
    float m = fmaxf(fmaxf(fmaxf(A0.x, A0.y), fmaxf(A0.z, A0.w)),
                    fmaxf(fmaxf(A1.x, A1.y), fmaxf(A1.z, A1.w)));
#pragma unroll
    for (int t = 0; t < 3; t++)
        m = fmaxf(m, fmaxf(fmaxf(L[t].x, L[t].y), fmaxf(L[t].z, L[t].w)));
#pragma unroll
    for (int o = 16; o > 0; o >>= 1)
        m = fmaxf(m, __shfl_xor_sync(0xFFFFFFFF, m, o));

    A0.x = __expf(A0.x - m); A0.y = __expf(A0.y - m);
    A0.z = __expf(A0.z - m); A0.w = __expf(A0.w - m);
    A1.x = __expf(A1.x - m); A1.y = __expf(A1.y - m);
    A1.z = __expf(A1.z - m); A1.w = __expf(A1.w - m);
#pragma unroll
    for (int t = 0; t < 3; t++) {
        L[t].x = __expf(L[t].x - m); L[t].y = __expf(L[t].y - m);
        L[t].z = __expf(L[t].z - m); L[t].w = __expf(L[t].w - m);
    }

    // sum: A-chunks are duplicated across half-warps -> count only hw==0
    float s = (hw == 0) ? (A0.x + A0.y + A0.z + A0.w + A1.x + A1.y + A1.z + A1.w) : 0.0f;
#pragma unroll
    for (int t = 0; t < 3; t++) s += L[t].x + L[t].y + L[t].z + L[t].w;
#pragma unroll
    for (int o = 16; o > 0; o >>= 1)
        s += __shfl_xor_sync(0xFFFFFFFF, s, o);

    float inv = __frcp_rn(s);
    A0.x *= inv; A0.y *= inv; A0.z *= inv; A0.w *= inv;
    A1.x *= inv; A1.y *= inv; A1.z *= inv; A1.w *= inv;
#pragma unroll
    for (int t = 0; t < 3; t++) {
        L[t].x *= inv; L[t].y *= inv; L[t].z *= inv; L[t].w *= inv;
        __stcs(orow + lane + 32 * t, L[t]);
    }
    __stcs(orow + 96 + 2 * c + hw, hw ? A1 : A0);
}

// ---------------------------------------------------------------------------
// Launch graph (4-stage column pipeline):
//   main: cvtW -> gemm q0..q3 (event after each)
//   side: zero -> count -> alloc -> fill -> [wait gq] agg q, q=0..3
// gemm q0 is the 4th submitted launch (ncu slot).
// ---------------------------------------------------------------------------
extern "C" void kernel_launch(void* const* d_in, const int* in_sizes, int n_in,
                              void* d_out, int out_size) {
    const float* onehot = (const float*)d_in[0];
    const int*   ei     = (const int*)d_in[1];    // [2, E]: src then dst
    const float* W      = (const float*)d_in[2];
    const float* b      = (const float*)d_in[3];
    float* out = (float*)d_out;

    static cudaStream_t side = nullptr;
    static cudaEvent_t evFork = nullptr, evJoin = nullptr, evG[4] = {};
    if (!side) {
        cudaStreamCreateWithFlags(&side, cudaStreamNonBlocking);
        cudaEventCreateWithFlags(&evFork, cudaEventDisableTiming);
        cudaEventCreateWithFlags(&evJoin, cudaEventDisableTiming);
        for (int q = 0; q < 4; q++)
            cudaEventCreateWithFlags(&evG[q], cudaEventDisableTiming);
        cudaFuncSetAttribute(gemm_kernel, cudaFuncAttributeMaxDynamicSharedMemorySize, SMEM_DYN);
    }

    cudaEventRecord(evFork, 0);
    cudaStreamWaitEvent(side, evFork, 0);

    const int gy = (N_NODES + BM - 1) / BM;

    cvtW_kernel<<<(N_FEAT * N_FEAT / 8 + 255) / 256, 256>>>(W);                   // #1
    zero_kernel<<<(N_NODES + 255) / 256, 256, 0, side>>>();                       // #2
    count_deg_kernel<<<(N_EDGES + 255) / 256, 256, 0, side>>>(ei + N_EDGES);      // #3
    gemm_kernel<<<dim3(1, gy), 256, SMEM_DYN>>>(onehot, 0);                       // #4 (ncu)
    cudaEventRecord(evG[0], 0);
    for (int q = 1; q < 4; q++) {
        gemm_kernel<<<dim3(1, gy), 256, SMEM_DYN>>>(onehot, q);
        cudaEventRecord(evG[q], 0);
    }

    alloc_kernel<<<(N_NODES + 255) / 256, 256, 0, side>>>();
    fill_kernel<<<(N_EDGES + 255) / 256, 256, 0, side>>>(ei);

    for (int q = 0; q < 3; q++) {
        cudaStreamWaitEvent(side, evG[q], 0);
        aggregate_q_kernel<<<(N_NODES + 7) / 8, 256, 0, side>>>(b, out, q);
    }
    cudaStreamWaitEvent(side, evG[3], 0);
    aggregate_q3_final_kernel<<<(N_NODES + 7) / 8, 256, 0, side>>>(b, out);

    cudaEventRecord(evJoin, side);
    cudaStreamWaitEvent(0, evJoin, 0);
}

// round 15
// speedup vs baseline: 1.0831x; 1.0831x over previous
#include <cuda_runtime.h>
#include <cuda_fp16.h>
#include <cstdint>

#define N_NODES 100000
#define N_FEAT  512
#define N_EDGES 3200000
#define NCH16   (N_FEAT / 8)   // 64 uint4 (8-half) chunks per row

// Scratch (allocation-free rule: __device__ globals)
__device__ __half g_wh[(size_t)N_FEAT * N_FEAT];   // W in fp16
__device__ __half g_xw[(size_t)N_NODES * N_FEAT];  // X @ W in fp16
__device__ float g_dinv[N_NODES];                  // rsqrt(deg+1)
__device__ int   g_deg[N_NODES];                   // in-degree (no self loop)
__device__ int   g_off[N_NODES];                   // CSR chunk start
__device__ int   g_cursor[N_NODES];                // fill cursor
__device__ int2  g_csr[N_EDGES];                   // {src, norm-bits} grouped by dst
__device__ int   g_total;                          // chunk allocator

// ---------------------------------------------------------------------------
// fp32 -> fp16 helpers
// ---------------------------------------------------------------------------
__device__ __forceinline__ uint4 cvt8(const float4 a, const float4 b) {
    __half2 h0 = __floats2half2_rn(a.x, a.y);
    __half2 h1 = __floats2half2_rn(a.z, a.w);
    __half2 h2 = __floats2half2_rn(b.x, b.y);
    __half2 h3 = __floats2half2_rn(b.z, b.w);
    uint4 v;
    v.x = *reinterpret_cast<unsigned*>(&h0);
    v.y = *reinterpret_cast<unsigned*>(&h1);
    v.z = *reinterpret_cast<unsigned*>(&h2);
    v.w = *reinterpret_cast<unsigned*>(&h3);
    return v;
}

__global__ void cvtW_kernel(const float* __restrict__ W) {
    int i = blockIdx.x * blockDim.x + threadIdx.x;   // over 512*512/8
    if (i < N_FEAT * N_FEAT / 8) {
        const float4* s = reinterpret_cast<const float4*>(W) + 2 * (size_t)i;
        reinterpret_cast<uint4*>(g_wh)[i] = cvt8(s[0], s[1]);
    }
}

// ---------------------------------------------------------------------------
// CSR build
// ---------------------------------------------------------------------------
__global__ void zero_kernel() {
    int i = blockIdx.x * blockDim.x + threadIdx.x;
    if (i < N_NODES) g_deg[i] = 0;
    if (i == 0) g_total = 0;
}

__global__ void count_deg_kernel(const int* __restrict__ dst) {
    int e = blockIdx.x * blockDim.x + threadIdx.x;
    if (e < N_EDGES) atomicAdd(&g_deg[__ldcs(dst + e)], 1);
}

__global__ void alloc_kernel() {
    int i = blockIdx.x * blockDim.x + threadIdx.x;
    if (i < N_NODES) {
        int d = g_deg[i];
        int o = atomicAdd(&g_total, d);   // disjoint contiguous ranges
        g_off[i] = o;
        g_cursor[i] = o;
        g_dinv[i] = rsqrtf((float)d + 1.0f);  // +1 = self loop
    }
}

__global__ void fill_kernel(const int* __restrict__ ei) {
    int e = blockIdx.x * blockDim.x + threadIdx.x;
    if (e < N_EDGES) {
        int s = __ldcs(ei + e);
        int d = __ldcs(ei + N_EDGES + e);
        int pos = atomicAdd(&g_cursor[d], 1);
        float nm = g_dinv[s] * g_dinv[d];   // dinv ready (fill after alloc)
        g_csr[pos] = make_int2(s, __float_as_int(nm));
    }
}

// ---------------------------------------------------------------------------
// GEMM: g_xw = fp16(onehot @ g_wh), fp16 mma m16n8k16 with fp32 accumulate.
// Launched twice (pass = column half). 128x128x32 tiles, 256 threads =
// 8 warps (2m x 4n), warp tile 64x32. 2 CTAs/SM. A converted in-register.
// ---------------------------------------------------------------------------
#define BM 128
#define BN 128
#define BK 32
#define SAH 40    // A smem row stride (halves)
#define SBH 136   // B smem row stride (halves)
#define A_BUF_H (BM * SAH)              // 5120 halves per buffer
#define B_BASE_H (2 * A_BUF_H)          // 10240
#define B_BUF_H (BK * SBH)              // 4352 halves per buffer
#define SMEM_DYN ((B_BASE_H + 2 * B_BUF_H) * 2)  // 37888 bytes

__device__ __forceinline__ unsigned smem_u32(const void* p) {
    return (unsigned)__cvta_generic_to_shared(p);
}

__device__ __forceinline__ void ldsm_x4(unsigned* r, const void* p) {
    asm volatile("ldmatrix.sync.aligned.m8n8.x4.shared.b16 {%0,%1,%2,%3}, [%4];"
                 : "=r"(r[0]), "=r"(r[1]), "=r"(r[2]), "=r"(r[3]) : "r"(smem_u32(p)));
}

__device__ __forceinline__ void ldsm_x4_trans(unsigned* r, const void* p) {
    asm volatile("ldmatrix.sync.aligned.m8n8.x4.trans.shared.b16 {%0,%1,%2,%3}, [%4];"
                 : "=r"(r[0]), "=r"(r[1]), "=r"(r[2]), "=r"(r[3]) : "r"(smem_u32(p)));
}

__device__ __forceinline__ void mma_f16(float* c, const unsigned* a, const unsigned* b) {
    asm volatile(
        "mma.sync.aligned.m16n8k16.row.col.f32.f16.f16.f32 "
        "{%0,%1,%2,%3}, {%4,%5,%6,%7}, {%8,%9}, {%0,%1,%2,%3};"
        : "+f"(c[0]), "+f"(c[1]), "+f"(c[2]), "+f"(c[3])
        : "r"(a[0]), "r"(a[1]), "r"(a[2]), "r"(a[3]), "r"(b[0]), "r"(b[1]));
}

__global__ __launch_bounds__(256, 2) void gemm_kernel(const float* __restrict__ A, int pass) {
    extern __shared__ __half sm[];

    const int tid = threadIdx.x;
    const int rowBase = blockIdx.y * BM;
    const int colBase = blockIdx.x * BN + pass * 256;

    // A: 128 rows x 32 fp32 -> 16 fp32 (4 float4) per thread.
    const int arow = tid >> 1;            // 0..127
    const int akc  = (tid & 1) * 16;      // 0 or 16
    // B: 32 k x 128 n halves -> 2 uint4 per thread.
    const int bk   = tid >> 3;            // 0..31
    const int bn   = (tid & 7) * 16;      // 0..112

    const float*  Aptr = A + (size_t)(rowBase + arow) * N_FEAT + akc;
    const __half* Bptr = g_wh + (size_t)bk * N_FEAT + colBase + bn;
    const bool arow_ok = (rowBase + arow) < N_NODES;

    // Warp tiling: 8 warps as 2(m) x 4(n); warp tile 64x32.
    const int warpId = tid >> 5;
    const int lane = tid & 31;
    const int wm = (warpId >> 2) * 64;    // 0 or 64
    const int wn = (warpId & 3) * 32;     // 0..96
    const int lr = lane & 15;             // ldmatrix row
    const int lc = (lane >> 4) * 8;       // ldmatrix col block
    const int qr = lane >> 2;             // mma c row
    const int qc = lane & 3;              // mma c col pair

    float acc[4][4][4] = {};              // [mi][ni][reg]

    float4 aR[4];
    uint4 bR[2];
#pragma unroll
    for (int j = 0; j < 4; j++)
        aR[j] = arow_ok ? __ldcs(reinterpret_cast<const float4*>(Aptr) + j)
                        : make_float4(0.f, 0.f, 0.f, 0.f);
    bR[0] = reinterpret_cast<const uint4*>(Bptr)[0];
    bR[1] = reinterpret_cast<const uint4*>(Bptr)[1];

    int buf = 0;
    for (int kb = 0; kb < N_FEAT; kb += BK) {
        *reinterpret_cast<uint4*>(&sm[buf * A_BUF_H + arow * SAH + akc])     = cvt8(aR[0], aR[1]);
        *reinterpret_cast<uint4*>(&sm[buf * A_BUF_H + arow * SAH + akc + 8]) = cvt8(aR[2], aR[3]);
        *reinterpret_cast<uint4*>(&sm[B_BASE_H + buf * B_BUF_H + bk * SBH + bn])     = bR[0];
        *reinterpret_cast<uint4*>(&sm[B_BASE_H + buf * B_BUF_H + bk * SBH + bn + 8]) = bR[1];
        __syncthreads();

        if (kb + BK < N_FEAT) {
            if (arow_ok) {
#pragma unroll
                for (int j = 0; j < 4; j++)
                    aR[j] = __ldcs(reinterpret_cast<const float4*>(Aptr + kb + BK) + j);
            }
            bR[0] = reinterpret_cast<const uint4*>(Bptr + (size_t)(kb + BK) * N_FEAT)[0];
            bR[1] = reinterpret_cast<const uint4*>(Bptr + (size_t)(kb + BK) * N_FEAT)[1];
        }

#pragma unroll
        for (int ks = 0; ks < 2; ks++) {
            const int k0 = ks * 16;
            unsigned af[4][4];
#pragma unroll
            for (int mi = 0; mi < 4; mi++)
                ldsm_x4(af[mi], &sm[buf * A_BUF_H + (wm + mi * 16 + lr) * SAH + k0 + lc]);
            unsigned bf[2][4];
#pragma unroll
            for (int nj = 0; nj < 2; nj++)
                ldsm_x4_trans(bf[nj], &sm[B_BASE_H + buf * B_BUF_H + (k0 + lr) * SBH + wn + nj * 16 + lc]);
#pragma unroll
            for (int mi = 0; mi < 4; mi++)
#pragma unroll
                for (int ni = 0; ni < 4; ni++)
                    mma_f16(acc[mi][ni], af[mi], &bf[ni >> 1][(ni & 1) * 2]);
        }
        __syncthreads();
        buf ^= 1;
    }

#pragma unroll
    for (int mi = 0; mi < 4; mi++) {
        const int r0 = rowBase + wm + mi * 16 + qr;
        const int r1 = r0 + 8;
#pragma unroll
        for (int ni = 0; ni < 4; ni++) {
            const int col = colBase + wn + ni * 8 + 2 * qc;
            if (r0 < N_NODES) {
                __half2 h = __floats2half2_rn(acc[mi][ni][0], acc[mi][ni][1]);
                *reinterpret_cast<__half2*>(&g_xw[(size_t)r0 * N_FEAT + col]) = h;
            }
            if (r1 < N_NODES) {
                __half2 h = __floats2half2_rn(acc[mi][ni][2], acc[mi][ni][3]);
                *reinterpret_cast<__half2*>(&g_xw[(size_t)r1 * N_FEAT + col]) = h;
            }
        }
    }
}

// ---------------------------------------------------------------------------
// Aggregate helpers. One warp per node, lane owns one uint4 (8 halves) of the
// 256-feature column half being processed.
// ---------------------------------------------------------------------------
__device__ __forceinline__ void acc_half8(float4& a0, float4& a1, uint4 raw, float m) {
    __half2 h0 = *reinterpret_cast<__half2*>(&raw.x);
    __half2 h1 = *reinterpret_cast<__half2*>(&raw.y);
    __half2 h2 = *reinterpret_cast<__half2*>(&raw.z);
    __half2 h3 = *reinterpret_cast<__half2*>(&raw.w);
    float2 f0 = __half22float2(h0);
    float2 f1 = __half22float2(h1);
    float2 f2 = __half22float2(h2);
    float2 f3 = __half22float2(h3);
    a0.x = fmaf(f0.x, m, a0.x); a0.y = fmaf(f0.y, m, a0.y);
    a0.z = fmaf(f1.x, m, a0.z); a0.w = fmaf(f1.y, m, a0.w);
    a1.x = fmaf(f2.x, m, a1.x); a1.y = fmaf(f2.y, m, a1.y);
    a1.z = fmaf(f3.x, m, a1.z); a1.w = fmaf(f3.y, m, a1.w);
}

// Gathers one column half for node n into (A0, A1), adds bias, applies relu.
__device__ __forceinline__ void gather_half(int n, int chunk, float4& A0, float4& A1,
                                            const float* __restrict__ bias) {
    const float dn = g_dinv[n];
    const uint4* __restrict__ xw4 = reinterpret_cast<const uint4*>(g_xw);

    A0 = make_float4(0.f, 0.f, 0.f, 0.f); A1 = A0;
    acc_half8(A0, A1, __ldcg(xw4 + (size_t)n * NCH16 + chunk), dn * dn);   // self loop

    const int start = g_off[n];
    const int cnt = g_deg[n];
    const int2* __restrict__ lst = g_csr + start;

    int i = 0;
    for (; i + 8 <= cnt; i += 8) {
        int2 e0 = __ldcs(lst + i),     e1 = __ldcs(lst + i + 1);
        int2 e2 = __ldcs(lst + i + 2), e3 = __ldcs(lst + i + 3);
        int2 e4 = __ldcs(lst + i + 4), e5 = __ldcs(lst + i + 5);
        int2 e6 = __ldcs(lst + i + 6), e7 = __ldcs(lst + i + 7);
        uint4 v0 = __ldcg(xw4 + (size_t)e0.x * NCH16 + chunk);
        uint4 v1 = __ldcg(xw4 + (size_t)e1.x * NCH16 + chunk);
        uint4 v2 = __ldcg(xw4 + (size_t)e2.x * NCH16 + chunk);
        uint4 v3 = __ldcg(xw4 + (size_t)e3.x * NCH16 + chunk);
        uint4 v4 = __ldcg(xw4 + (size_t)e4.x * NCH16 + chunk);
        uint4 v5 = __ldcg(xw4 + (size_t)e5.x * NCH16 + chunk);
        uint4 v6 = __ldcg(xw4 + (size_t)e6.x * NCH16 + chunk);
        uint4 v7 = __ldcg(xw4 + (size_t)e7.x * NCH16 + chunk);
        acc_half8(A0, A1, v0, __int_as_float(e0.y));
        acc_half8(A0, A1, v1, __int_as_float(e1.y));
        acc_half8(A0, A1, v2, __int_as_float(e2.y));
        acc_half8(A0, A1, v3, __int_as_float(e3.y));
        acc_half8(A0, A1, v4, __int_as_float(e4.y));
        acc_half8(A0, A1, v5, __int_as_float(e5.y));
        acc_half8(A0, A1, v6, __int_as_float(e6.y));
        acc_half8(A0, A1, v7, __int_as_float(e7.y));
    }
    for (; i < cnt; i++) {
        int2 e = __ldcs(lst + i);
        acc_half8(A0, A1, __ldcg(xw4 + (size_t)e.x * NCH16 + chunk), __int_as_float(e.y));
    }

    const float4* b4 = reinterpret_cast<const float4*>(bias);
    float4 ba0 = b4[2 * chunk], ba1 = b4[2 * chunk + 1];
    A0.x = fmaxf(A0.x + ba0.x, 0.f); A0.y = fmaxf(A0.y + ba0.y, 0.f);
    A0.z = fmaxf(A0.z + ba0.z, 0.f); A0.w = fmaxf(A0.w + ba0.w, 0.f);
    A1.x = fmaxf(A1.x + ba1.x, 0.f); A1.y = fmaxf(A1.y + ba1.y, 0.f);
    A1.z = fmaxf(A1.z + ba1.z, 0.f); A1.w = fmaxf(A1.w + ba1.w, 0.f);
}

// Half 0: write relu'd logits to out (columns 0..255).
__global__ __launch_bounds__(256) void aggregate_half0_kernel(const float* __restrict__ bias,
                                                              float* __restrict__ out) {
    const int n = blockIdx.x * 8 + (threadIdx.x >> 5);
    if (n >= N_NODES) return;
    const int lane = threadIdx.x & 31;
    float4 A0, A1;
    gather_half(n, lane, A0, A1, bias);
    float4* orow = reinterpret_cast<float4*>(out) + (size_t)n * (N_FEAT / 4);
    __stcs(orow + 2 * lane,     A0);
    __stcs(orow + 2 * lane + 1, A1);
}

// Half 1 + fused softmax: gather columns 256..511, re-read half-0 logits,
// normalize the full row, and write everything once.
__global__ __launch_bounds__(256) void aggregate_half1_final_kernel(const float* __restrict__ bias,
                                                                    float* __restrict__ out) {
    const int n = blockIdx.x * 8 + (threadIdx.x >> 5);
    if (n >= N_NODES) return;
    const int lane = threadIdx.x & 31;
    float4 A0, A1;
    gather_half(n, 32 + lane, A0, A1, bias);

    float4* orow = reinterpret_cast<float4*>(out) + (size_t)n * (N_FEAT / 4);
    float4 L0 = __ldcg(orow + 2 * lane);        // half-0 logits (relu'd)
    float4 L1 = __ldcg(orow + 2 * lane + 1);

    // row max (relu output >= 0 so 0 is a valid floor)
    float m = fmaxf(fmaxf(fmaxf(A0.x, A0.y), fmaxf(A0.z, A0.w)),
                    fmaxf(fmaxf(A1.x, A1.y), fmaxf(A1.z, A1.w)));
    m = fmaxf(m, fmaxf(fmaxf(fmaxf(L0.x, L0.y), fmaxf(L0.z, L0.w)),
                       fmaxf(fmaxf(L1.x, L1.y), fmaxf(L1.z, L1.w))));
#pragma unroll
    for (int o = 16; o > 0; o >>= 1)
        m = fmaxf(m, __shfl_xor_sync(0xFFFFFFFF, m, o));

    A0.x = __expf(A0.x - m); A0.y = __expf(A0.y - m);
    A0.z = __expf(A0.z - m); A0.w = __expf(A0.w - m);
    A1.x = __expf(A1.x - m); A1.y = __expf(A1.y - m);
    A1.z = __expf(A1.z - m); A1.w = __expf(A1.w - m);
    L0.x = __expf(L0.x - m); L0.y = __expf(L0.y - m);
    L0.z = __expf(L0.z - m); L0.w = __expf(L0.w - m);
    L1.x = __expf(L1.x - m); L1.y = __expf(L1.y - m);
    L1.z = __expf(L1.z - m); L1.w = __expf(L1.w - m);

    float s = A0.x + A0.y + A0.z + A0.w + A1.x + A1.y + A1.z + A1.w +
              L0.x + L0.y + L0.z + L0.w + L1.x + L1.y + L1.z + L1.w;
#pragma unroll
    for (int o = 16; o > 0; o >>= 1)
        s += __shfl_xor_sync(0xFFFFFFFF, s, o);

    float inv = __frcp_rn(s);
    A0.x *= inv; A0.y *= inv; A0.z *= inv; A0.w *= inv;
    A1.x *= inv; A1.y *= inv; A1.z *= inv; A1.w *= inv;
    L0.x *= inv; L0.y *= inv; L0.z *= inv; L0.w *= inv;
    L1.x *= inv; L1.y *= inv; L1.z *= inv; L1.w *= inv;

    __stcs(orow + 2 * lane,              L0);
    __stcs(orow + 2 * lane + 1,          L1);
    __stcs(orow + 2 * (32 + lane),       A0);
    __stcs(orow + 2 * (32 + lane) + 1,   A1);
}

// ---------------------------------------------------------------------------
// Launch graph:
//   main: cvtW -> gemmA(evA) -> gemmB(evB)
//   side: zero -> count -> alloc -> fill -> [wait evA] agg0 -> [wait evB]
//         agg1+softmax -> (join main)
// gemmA is the 4th submitted launch (ncu slot).
// ---------------------------------------------------------------------------
extern "C" void kernel_launch(void* const* d_in, const int* in_sizes, int n_in,
                              void* d_out, int out_size) {
    const float* onehot = (const float*)d_in[0];
    const int*   ei     = (const int*)d_in[1];    // [2, E]: src then dst
    const float* W      = (const float*)d_in[2];
    const float* b      = (const float*)d_in[3];
    float* out = (float*)d_out;

    static cudaStream_t side = nullptr;
    static cudaEvent_t evFork = nullptr, evA = nullptr, evB = nullptr, evJoin = nullptr;
    if (!side) {
        cudaStreamCreateWithFlags(&side, cudaStreamNonBlocking);
        cudaEventCreateWithFlags(&evFork, cudaEventDisableTiming);
        cudaEventCreateWithFlags(&evA, cudaEventDisableTiming);
        cudaEventCreateWithFlags(&evB, cudaEventDisableTiming);
        cudaEventCreateWithFlags(&evJoin, cudaEventDisableTiming);
        cudaFuncSetAttribute(gemm_kernel, cudaFuncAttributeMaxDynamicSharedMemorySize, SMEM_DYN);
    }

    cudaEventRecord(evFork, 0);
    cudaStreamWaitEvent(side, evFork, 0);

    const int gy = (N_NODES + BM - 1) / BM;

    cvtW_kernel<<<(N_FEAT * N_FEAT / 8 + 255) / 256, 256>>>(W);                   // #1
    zero_kernel<<<(N_NODES + 255) / 256, 256, 0, side>>>();                       // #2
    count_deg_kernel<<<(N_EDGES + 255) / 256, 256, 0, side>>>(ei + N_EDGES);      // #3
    gemm_kernel<<<dim3(2, gy), 256, SMEM_DYN>>>(onehot, 0);                       // #4 (ncu)
    cudaEventRecord(evA, 0);
    gemm_kernel<<<dim3(2, gy), 256, SMEM_DYN>>>(onehot, 1);
    cudaEventRecord(evB, 0);

    alloc_kernel<<<(N_NODES + 255) / 256, 256, 0, side>>>();
    fill_kernel<<<(N_EDGES + 255) / 256, 256, 0, side>>>(ei);

    cudaStreamWaitEvent(side, evA, 0);
    aggregate_half0_kernel<<<(N_NODES + 7) / 8, 256, 0, side>>>(b, out);
    cudaStreamWaitEvent(side, evB, 0);
    aggregate_half1_final_kernel<<<(N_NODES + 7) / 8, 256, 0, side>>>(b, out);

    cudaEventRecord(evJoin, side);
    cudaStreamWaitEvent(0, evJoin, 0);
}

// round 16
// speedup vs baseline: 1.1649x; 1.0755x over previous
#include <cuda_runtime.h>
#include <cuda_fp16.h>
#include <cstdint>

#define N_NODES 100000
#define N_FEAT  512
#define N_EDGES 3200000
#define NCH16   (N_FEAT / 8)   // 64 uint4 (8-half) chunks per row

// Scratch (allocation-free rule: __device__ globals)
__device__ __half g_wh[(size_t)N_FEAT * N_FEAT];   // W in fp16
__device__ __half g_xw[(size_t)N_NODES * N_FEAT];  // X @ W in fp16
__device__ __half g_l0[(size_t)N_NODES * 256];     // half-0 relu'd logits (fp16 staging)
__device__ float g_dinv[N_NODES];                  // rsqrt(deg+1)
__device__ int   g_deg[N_NODES];                   // in-degree (no self loop)
__device__ int   g_off[N_NODES];                   // CSR chunk start
__device__ int   g_cursor[N_NODES];                // fill cursor
__device__ int2  g_csr[N_EDGES];                   // {src, norm-bits} grouped by dst
__device__ int   g_total;                          // chunk allocator

// ---------------------------------------------------------------------------
// fp32 -> fp16 helpers
// ---------------------------------------------------------------------------
__device__ __forceinline__ uint4 cvt8(const float4 a, const float4 b) {
    __half2 h0 = __floats2half2_rn(a.x, a.y);
    __half2 h1 = __floats2half2_rn(a.z, a.w);
    __half2 h2 = __floats2half2_rn(b.x, b.y);
    __half2 h3 = __floats2half2_rn(b.z, b.w);
    uint4 v;
    v.x = *reinterpret_cast<unsigned*>(&h0);
    v.y = *reinterpret_cast<unsigned*>(&h1);
    v.z = *reinterpret_cast<unsigned*>(&h2);
    v.w = *reinterpret_cast<unsigned*>(&h3);
    return v;
}

__global__ void cvtW_kernel(const float* __restrict__ W) {
    int i = blockIdx.x * blockDim.x + threadIdx.x;   // over 512*512/8
    if (i < N_FEAT * N_FEAT / 8) {
        const float4* s = reinterpret_cast<const float4*>(W) + 2 * (size_t)i;
        reinterpret_cast<uint4*>(g_wh)[i] = cvt8(s[0], s[1]);
    }
}

// ---------------------------------------------------------------------------
// CSR build
// ---------------------------------------------------------------------------
__global__ void zero_kernel() {
    int i = blockIdx.x * blockDim.x + threadIdx.x;
    if (i < N_NODES) g_deg[i] = 0;
    if (i == 0) g_total = 0;
}

__global__ void count_deg_kernel(const int* __restrict__ dst) {
    int e = blockIdx.x * blockDim.x + threadIdx.x;
    if (e < N_EDGES) atomicAdd(&g_deg[__ldcs(dst + e)], 1);
}

__global__ void alloc_kernel() {
    int i = blockIdx.x * blockDim.x + threadIdx.x;
    if (i < N_NODES) {
        int d = g_deg[i];
        int o = atomicAdd(&g_total, d);   // disjoint contiguous ranges
        g_off[i] = o;
        g_cursor[i] = o;
        g_dinv[i] = rsqrtf((float)d + 1.0f);  // +1 = self loop
    }
}

__global__ void fill_kernel(const int* __restrict__ ei) {
    int e = blockIdx.x * blockDim.x + threadIdx.x;
    if (e < N_EDGES) {
        int s = __ldcs(ei + e);
        int d = __ldcs(ei + N_EDGES + e);
        int pos = atomicAdd(&g_cursor[d], 1);
        float nm = g_dinv[s] * g_dinv[d];   // dinv ready (fill after alloc)
        g_csr[pos] = make_int2(s, __float_as_int(nm));
    }
}

// ---------------------------------------------------------------------------
// GEMM: g_xw = fp16(onehot @ g_wh), fp16 mma m16n8k16 with fp32 accumulate.
// Launched twice (pass = column half) so aggregation can start after half 1.
// 256x128x32 block tile, 256 threads = 8 warps (4m x 2n), warp tile 64x64.
// ---------------------------------------------------------------------------
#define BM 256
#define BN 128
#define BK 32
#define SAH 40    // A smem row stride (halves)
#define SBH 136   // B smem row stride (halves)
#define A_BUF_H (BM * SAH)              // 10240 halves per buffer
#define B_BASE_H (2 * A_BUF_H)          // 20480
#define B_BUF_H (BK * SBH)              // 4352 halves per buffer
#define SMEM_DYN ((B_BASE_H + 2 * B_BUF_H) * 2)  // 58368 bytes

__device__ __forceinline__ unsigned smem_u32(const void* p) {
    return (unsigned)__cvta_generic_to_shared(p);
}

__device__ __forceinline__ void ldsm_x4(unsigned* r, const void* p) {
    asm volatile("ldmatrix.sync.aligned.m8n8.x4.shared.b16 {%0,%1,%2,%3}, [%4];"
                 : "=r"(r[0]), "=r"(r[1]), "=r"(r[2]), "=r"(r[3]) : "r"(smem_u32(p)));
}

__device__ __forceinline__ void ldsm_x4_trans(unsigned* r, const void* p) {
    asm volatile("ldmatrix.sync.aligned.m8n8.x4.trans.shared.b16 {%0,%1,%2,%3}, [%4];"
                 : "=r"(r[0]), "=r"(r[1]), "=r"(r[2]), "=r"(r[3]) : "r"(smem_u32(p)));
}

__device__ __forceinline__ void mma_f16(float* c, const unsigned* a, const unsigned* b) {
    asm volatile(
        "mma.sync.aligned.m16n8k16.row.col.f32.f16.f16.f32 "
        "{%0,%1,%2,%3}, {%4,%5,%6,%7}, {%8,%9}, {%0,%1,%2,%3};"
        : "+f"(c[0]), "+f"(c[1]), "+f"(c[2]), "+f"(c[3])
        : "r"(a[0]), "r"(a[1]), "r"(a[2]), "r"(a[3]), "r"(b[0]), "r"(b[1]));
}

__global__ __launch_bounds__(256, 1) void gemm_kernel(const float* __restrict__ A, int pass) {
    extern __shared__ __half sm[];

    const int tid = threadIdx.x;
    const int rowBase = blockIdx.y * BM;
    const int colBase = (blockIdx.x + 2 * pass) * BN;

    const int arow = tid >> 2;            // 0..63 (+64*i)
    const int akc  = (tid & 3) * 8;       // 0,8,16,24
    const int bk   = tid >> 4;            // 0..15 (+16*j)
    const int bn   = (tid & 15) * 8;      // 0..120

    const float*  Aptr = A + (size_t)(rowBase + arow) * N_FEAT + akc;
    const __half* Bptr = g_wh + (size_t)bk * N_FEAT + colBase + bn;

    bool aok[4];
#pragma unroll
    for (int i = 0; i < 4; i++) aok[i] = (rowBase + arow + 64 * i) < N_NODES;

    const int warpId = tid >> 5;
    const int lane = tid & 31;
    const int wm = (warpId >> 1) * 64;    // 0,64,128,192
    const int wn = (warpId & 1) * 64;     // 0,64
    const int lr = lane & 15;             // ldmatrix row
    const int lc = (lane >> 4) * 8;       // ldmatrix col block
    const int qr = lane >> 2;             // mma c row
    const int qc = lane & 3;              // mma c col pair

    float acc[4][8][4] = {};              // [mi][ni][reg]

    float4 aR[4][2];
    uint4 bR[2];
#pragma unroll
    for (int i = 0; i < 4; i++) {
        if (aok[i]) {
            aR[i][0] = __ldcs(reinterpret_cast<const float4*>(Aptr + (size_t)64 * i * N_FEAT));
            aR[i][1] = __ldcs(reinterpret_cast<const float4*>(Aptr + (size_t)64 * i * N_FEAT + 4));
        } else {
            aR[i][0] = aR[i][1] = make_float4(0.f, 0.f, 0.f, 0.f);
        }
    }
#pragma unroll
    for (int j = 0; j < 2; j++)
        bR[j] = *reinterpret_cast<const uint4*>(Bptr + (size_t)16 * j * N_FEAT);

    int buf = 0;
    for (int kb = 0; kb < N_FEAT; kb += BK) {
#pragma unroll
        for (int i = 0; i < 4; i++)
            *reinterpret_cast<uint4*>(&sm[buf * A_BUF_H + (arow + 64 * i) * SAH + akc]) =
                cvt8(aR[i][0], aR[i][1]);
#pragma unroll
        for (int j = 0; j < 2; j++)
            *reinterpret_cast<uint4*>(&sm[B_BASE_H + buf * B_BUF_H + (bk + 16 * j) * SBH + bn]) = bR[j];
        __syncthreads();

        if (kb + BK < N_FEAT) {
#pragma unroll
            for (int i = 0; i < 4; i++)
                if (aok[i]) {
                    aR[i][0] = __ldcs(reinterpret_cast<const float4*>(
                        Aptr + (size_t)64 * i * N_FEAT + kb + BK));
                    aR[i][1] = __ldcs(reinterpret_cast<const float4*>(
                        Aptr + (size_t)64 * i * N_FEAT + kb + BK + 4));
                }
#pragma unroll
            for (int j = 0; j < 2; j++)
                bR[j] = *reinterpret_cast<const uint4*>(
                    Bptr + (size_t)(kb + BK + 16 * j) * N_FEAT);
        }

#pragma unroll
        for (int ks = 0; ks < 2; ks++) {
            const int k0 = ks * 16;
            unsigned af[4][4];
#pragma unroll
            for (int mi = 0; mi < 4; mi++)
                ldsm_x4(af[mi], &sm[buf * A_BUF_H + (wm + mi * 16 + lr) * SAH + k0 + lc]);
            unsigned bf[4][4];
#pragma unroll
            for (int nj = 0; nj < 4; nj++)
                ldsm_x4_trans(bf[nj], &sm[B_BASE_H + buf * B_BUF_H + (k0 + lr) * SBH + wn + nj * 16 + lc]);
#pragma unroll
            for (int mi = 0; mi < 4; mi++)
#pragma unroll
                for (int ni = 0; ni < 8; ni++)
                    mma_f16(acc[mi][ni], af[mi], &bf[ni >> 1][(ni & 1) * 2]);
        }
        __syncthreads();
        buf ^= 1;
    }

#pragma unroll
    for (int mi = 0; mi < 4; mi++) {
        const int r0 = rowBase + wm + mi * 16 + qr;
        const int r1 = r0 + 8;
#pragma unroll
        for (int ni = 0; ni < 8; ni++) {
            const int col = colBase + wn + ni * 8 + 2 * qc;
            if (r0 < N_NODES) {
                __half2 h = __floats2half2_rn(acc[mi][ni][0], acc[mi][ni][1]);
                *reinterpret_cast<__half2*>(&g_xw[(size_t)r0 * N_FEAT + col]) = h;
            }
            if (r1 < N_NODES) {
                __half2 h = __floats2half2_rn(acc[mi][ni][2], acc[mi][ni][3]);
                *reinterpret_cast<__half2*>(&g_xw[(size_t)r1 * N_FEAT + col]) = h;
            }
        }
    }
}

// ---------------------------------------------------------------------------
// Aggregate helpers. One warp per node, lane owns one uint4 (8 halves) of the
// 256-feature column half being processed.
// ---------------------------------------------------------------------------
__device__ __forceinline__ void acc_half8(float4& a0, float4& a1, uint4 raw, float m) {
    __half2 h0 = *reinterpret_cast<__half2*>(&raw.x);
    __half2 h1 = *reinterpret_cast<__half2*>(&raw.y);
    __half2 h2 = *reinterpret_cast<__half2*>(&raw.z);
    __half2 h3 = *reinterpret_cast<__half2*>(&raw.w);
    float2 f0 = __half22float2(h0);
    float2 f1 = __half22float2(h1);
    float2 f2 = __half22float2(h2);
    float2 f3 = __half22float2(h3);
    a0.x = fmaf(f0.x, m, a0.x); a0.y = fmaf(f0.y, m, a0.y);
    a0.z = fmaf(f1.x, m, a0.z); a0.w = fmaf(f1.y, m, a0.w);
    a1.x = fmaf(f2.x, m, a1.x); a1.y = fmaf(f2.y, m, a1.y);
    a1.z = fmaf(f3.x, m, a1.z); a1.w = fmaf(f3.y, m, a1.w);
}

// Gathers one column half for node n into (A0, A1), adds bias, applies relu.
__device__ __forceinline__ void gather_half(int n, int chunk, float4& A0, float4& A1,
                                            const float* __restrict__ bias) {
    const float dn = g_dinv[n];
    const uint4* __restrict__ xw4 = reinterpret_cast<const uint4*>(g_xw);

    A0 = make_float4(0.f, 0.f, 0.f, 0.f); A1 = A0;
    acc_half8(A0, A1, __ldcg(xw4 + (size_t)n * NCH16 + chunk), dn * dn);   // self loop

    const int start = g_off[n];
    const int cnt = g_deg[n];
    const int2* __restrict__ lst = g_csr + start;

    int i = 0;
    for (; i + 8 <= cnt; i += 8) {
        int2 e0 = __ldcs(lst + i),     e1 = __ldcs(lst + i + 1);
        int2 e2 = __ldcs(lst + i + 2), e3 = __ldcs(lst + i + 3);
        int2 e4 = __ldcs(lst + i + 4), e5 = __ldcs(lst + i + 5);
        int2 e6 = __ldcs(lst + i + 6), e7 = __ldcs(lst + i + 7);
        uint4 v0 = __ldcg(xw4 + (size_t)e0.x * NCH16 + chunk);
        uint4 v1 = __ldcg(xw4 + (size_t)e1.x * NCH16 + chunk);
        uint4 v2 = __ldcg(xw4 + (size_t)e2.x * NCH16 + chunk);
        uint4 v3 = __ldcg(xw4 + (size_t)e3.x * NCH16 + chunk);
        uint4 v4 = __ldcg(xw4 + (size_t)e4.x * NCH16 + chunk);
        uint4 v5 = __ldcg(xw4 + (size_t)e5.x * NCH16 + chunk);
        uint4 v6 = __ldcg(xw4 + (size_t)e6.x * NCH16 + chunk);
        uint4 v7 = __ldcg(xw4 + (size_t)e7.x * NCH16 + chunk);
        acc_half8(A0, A1, v0, __int_as_float(e0.y));
        acc_half8(A0, A1, v1, __int_as_float(e1.y));
        acc_half8(A0, A1, v2, __int_as_float(e2.y));
        acc_half8(A0, A1, v3, __int_as_float(e3.y));
        acc_half8(A0, A1, v4, __int_as_float(e4.y));
        acc_half8(A0, A1, v5, __int_as_float(e5.y));
        acc_half8(A0, A1, v6, __int_as_float(e6.y));
        acc_half8(A0, A1, v7, __int_as_float(e7.y));
    }
    for (; i < cnt; i++) {
        int2 e = __ldcs(lst + i);
        acc_half8(A0, A1, __ldcg(xw4 + (size_t)e.x * NCH16 + chunk), __int_as_float(e.y));
    }

    const float4* b4 = reinterpret_cast<const float4*>(bias);
    float4 ba0 = b4[2 * chunk], ba1 = b4[2 * chunk + 1];
    A0.x = fmaxf(A0.x + ba0.x, 0.f); A0.y = fmaxf(A0.y + ba0.y, 0.f);
    A0.z = fmaxf(A0.z + ba0.z, 0.f); A0.w = fmaxf(A0.w + ba0.w, 0.f);
    A1.x = fmaxf(A1.x + ba1.x, 0.f); A1.y = fmaxf(A1.y + ba1.y, 0.f);
    A1.z = fmaxf(A1.z + ba1.z, 0.f); A1.w = fmaxf(A1.w + ba1.w, 0.f);
}

// Half 0: write relu'd logits to fp16 staging buffer g_l0.
__global__ __launch_bounds__(256) void aggregate_half0_kernel(const float* __restrict__ bias) {
    const int n = blockIdx.x * 8 + (threadIdx.x >> 5);
    if (n >= N_NODES) return;
    const int lane = threadIdx.x & 31;
    float4 A0, A1;
    gather_half(n, lane, A0, A1, bias);
    __half2 h0 = __floats2half2_rn(A0.x, A0.y);
    __half2 h1 = __floats2half2_rn(A0.z, A0.w);
    __half2 h2 = __floats2half2_rn(A1.x, A1.y);
    __half2 h3 = __floats2half2_rn(A1.z, A1.w);
    uint4 v;
    v.x = *reinterpret_cast<unsigned*>(&h0);
    v.y = *reinterpret_cast<unsigned*>(&h1);
    v.z = *reinterpret_cast<unsigned*>(&h2);
    v.w = *reinterpret_cast<unsigned*>(&h3);
    __stcs(reinterpret_cast<uint4*>(g_l0) + (size_t)n * 32 + lane, v);
}

// Half 1 + fused softmax: gather columns 256..511, read fp16 half-0 logits,
// normalize the full row, and write the fp32 output once.
__global__ __launch_bounds__(256) void aggregate_half1_final_kernel(const float* __restrict__ bias,
                                                                    float* __restrict__ out) {
    const int n = blockIdx.x * 8 + (threadIdx.x >> 5);
    if (n >= N_NODES) return;
    const int lane = threadIdx.x & 31;
    float4 A0, A1;
    gather_half(n, 32 + lane, A0, A1, bias);

    uint4 raw = __ldcg(reinterpret_cast<const uint4*>(g_l0) + (size_t)n * 32 + lane);
    __half2 h0 = *reinterpret_cast<__half2*>(&raw.x);
    __half2 h1 = *reinterpret_cast<__half2*>(&raw.y);
    __half2 h2 = *reinterpret_cast<__half2*>(&raw.z);
    __half2 h3 = *reinterpret_cast<__half2*>(&raw.w);
    float2 f0 = __half22float2(h0), f1 = __half22float2(h1);
    float2 f2 = __half22float2(h2), f3 = __half22float2(h3);
    float4 L0 = make_float4(f0.x, f0.y, f1.x, f1.y);
    float4 L1 = make_float4(f2.x, f2.y, f3.x, f3.y);

    // row max (relu output >= 0 so 0 is a valid floor)
    float m = fmaxf(fmaxf(fmaxf(A0.x, A0.y), fmaxf(A0.z, A0.w)),
                    fmaxf(fmaxf(A1.x, A1.y), fmaxf(A1.z, A1.w)));
    m = fmaxf(m, fmaxf(fmaxf(fmaxf(L0.x, L0.y), fmaxf(L0.z, L0.w)),
                       fmaxf(fmaxf(L1.x, L1.y), fmaxf(L1.z, L1.w))));
#pragma unroll
    for (int o = 16; o > 0; o >>= 1)
        m = fmaxf(m, __shfl_xor_sync(0xFFFFFFFF, m, o));

    A0.x = __expf(A0.x - m); A0.y = __expf(A0.y - m);
    A0.z = __expf(A0.z - m); A0.w = __expf(A0.w - m);
    A1.x = __expf(A1.x - m); A1.y = __expf(A1.y - m);
    A1.z = __expf(A1.z - m); A1.w = __expf(A1.w - m);
    L0.x = __expf(L0.x - m); L0.y = __expf(L0.y - m);
    L0.z = __expf(L0.z - m); L0.w = __expf(L0.w - m);
    L1.x = __expf(L1.x - m); L1.y = __expf(L1.y - m);
    L1.z = __expf(L1.z - m); L1.w = __expf(L1.w - m);

    float s = A0.x + A0.y + A0.z + A0.w + A1.x + A1.y + A1.z + A1.w +
              L0.x + L0.y + L0.z + L0.w + L1.x + L1.y + L1.z + L1.w;
#pragma unroll
    for (int o = 16; o > 0; o >>= 1)
        s += __shfl_xor_sync(0xFFFFFFFF, s, o);

    float inv = __frcp_rn(s);
    A0.x *= inv; A0.y *= inv; A0.z *= inv; A0.w *= inv;
    A1.x *= inv; A1.y *= inv; A1.z *= inv; A1.w *= inv;
    L0.x *= inv; L0.y *= inv; L0.z *= inv; L0.w *= inv;
    L1.x *= inv; L1.y *= inv; L1.z *= inv; L1.w *= inv;

    float4* orow = reinterpret_cast<float4*>(out) + (size_t)n * (N_FEAT / 4);
    __stcs(orow + 2 * lane,              L0);
    __stcs(orow + 2 * lane + 1,          L1);
    __stcs(orow + 2 * (32 + lane),       A0);
    __stcs(orow + 2 * (32 + lane) + 1,   A1);
}

// ---------------------------------------------------------------------------
// Launch graph:
//   main: cvtW -> gemmA(evA) -> gemmB(evB)
//   side: zero -> count -> alloc -> fill -> [wait evA] agg0 -> [wait evB]
//         agg1+softmax -> (join main)
// gemmA is the 4th submitted launch (ncu slot).
// ---------------------------------------------------------------------------
extern "C" void kernel_launch(void* const* d_in, const int* in_sizes, int n_in,
                              void* d_out, int out_size) {
    const float* onehot = (const float*)d_in[0];
    const int*   ei     = (const int*)d_in[1];    // [2, E]: src then dst
    const float* W      = (const float*)d_in[2];
    const float* b      = (const float*)d_in[3];
    float* out = (float*)d_out;

    static cudaStream_t side = nullptr;
    static cudaEvent_t evFork = nullptr, evA = nullptr, evB = nullptr, evJoin = nullptr;
    if (!side) {
        cudaStreamCreateWithFlags(&side, cudaStreamNonBlocking);
        cudaEventCreateWithFlags(&evFork, cudaEventDisableTiming);
        cudaEventCreateWithFlags(&evA, cudaEventDisableTiming);
        cudaEventCreateWithFlags(&evB, cudaEventDisableTiming);
        cudaEventCreateWithFlags(&evJoin, cudaEventDisableTiming);
        cudaFuncSetAttribute(gemm_kernel, cudaFuncAttributeMaxDynamicSharedMemorySize, SMEM_DYN);
    }

    cudaEventRecord(evFork, 0);
    cudaStreamWaitEvent(side, evFork, 0);

    const int gy = (N_NODES + BM - 1) / BM;

    cvtW_kernel<<<(N_FEAT * N_FEAT / 8 + 255) / 256, 256>>>(W);                   // #1
    zero_kernel<<<(N_NODES + 255) / 256, 256, 0, side>>>();                       // #2
    count_deg_kernel<<<(N_EDGES + 255) / 256, 256, 0, side>>>(ei + N_EDGES);      // #3
    gemm_kernel<<<dim3(2, gy), 256, SMEM_DYN>>>(onehot, 0);                       // #4 (ncu)
    cudaEventRecord(evA, 0);
    gemm_kernel<<<dim3(2, gy), 256, SMEM_DYN>>>(onehot, 1);
    cudaEventRecord(evB, 0);

    alloc_kernel<<<(N_NODES + 255) / 256, 256, 0, side>>>();
    fill_kernel<<<(N_EDGES + 255) / 256, 256, 0, side>>>(ei);

    cudaStreamWaitEvent(side, evA, 0);
    aggregate_half0_kernel<<<(N_NODES + 7) / 8, 256, 0, side>>>(b);
    cudaStreamWaitEvent(side, evB, 0);
    aggregate_half1_final_kernel<<<(N_NODES + 7) / 8, 256, 0, side>>>(b, out);

    cudaEventRecord(evJoin, side);
    cudaStreamWaitEvent(0, evJoin, 0);
}

// round 17
// speedup vs baseline: 1.1981x; 1.0285x over previous
#include <cuda_runtime.h>
#include <cuda_fp16.h>
#include <cstdint>

#define N_NODES 100000
#define N_FEAT  512
#define N_EDGES 3200000
#define NCH16   (N_FEAT / 8)   // 64 uint4 (8-half) chunks per row

// Scratch (allocation-free rule: __device__ globals)
__device__ __half g_wh[(size_t)N_FEAT * N_FEAT];   // W in fp16
__device__ __half g_xw[(size_t)N_NODES * N_FEAT];  // X @ W in fp16
__device__ __half g_l0[(size_t)N_NODES * 256];     // half-0 relu'd logits (fp16 staging)
__device__ float g_dinv[N_NODES];                  // rsqrt(deg+1)
__device__ int   g_deg[N_NODES];                   // in-degree (no self loop)
__device__ int   g_off[N_NODES];                   // CSR chunk start
__device__ int   g_cursor[N_NODES];                // fill cursor
__device__ int2  g_csr[N_EDGES];                   // {src, norm-bits} grouped by dst
__device__ int   g_total;                          // chunk allocator
__device__ int   g_ctr0, g_ctr1;                   // work-stealing counters

// ---------------------------------------------------------------------------
// fp32 -> fp16 helpers
// ---------------------------------------------------------------------------
__device__ __forceinline__ uint4 cvt8(const float4 a, const float4 b) {
    __half2 h0 = __floats2half2_rn(a.x, a.y);
    __half2 h1 = __floats2half2_rn(a.z, a.w);
    __half2 h2 = __floats2half2_rn(b.x, b.y);
    __half2 h3 = __floats2half2_rn(b.z, b.w);
    uint4 v;
    v.x = *reinterpret_cast<unsigned*>(&h0);
    v.y = *reinterpret_cast<unsigned*>(&h1);
    v.z = *reinterpret_cast<unsigned*>(&h2);
    v.w = *reinterpret_cast<unsigned*>(&h3);
    return v;
}

__global__ void cvtW_kernel(const float* __restrict__ W) {
    int i = blockIdx.x * blockDim.x + threadIdx.x;   // over 512*512/8
    if (i < N_FEAT * N_FEAT / 8) {
        const float4* s = reinterpret_cast<const float4*>(W) + 2 * (size_t)i;
        reinterpret_cast<uint4*>(g_wh)[i] = cvt8(s[0], s[1]);
    }
}

// ---------------------------------------------------------------------------
// CSR build
// ---------------------------------------------------------------------------
__global__ void zero_kernel() {
    int i = blockIdx.x * blockDim.x + threadIdx.x;
    if (i < N_NODES) g_deg[i] = 0;
    if (i == 0) { g_total = 0; g_ctr0 = 0; g_ctr1 = 0; }
}

__global__ void count_deg_kernel(const int* __restrict__ dst) {
    int e = blockIdx.x * blockDim.x + threadIdx.x;
    if (e < N_EDGES) atomicAdd(&g_deg[__ldcs(dst + e)], 1);
}

__global__ void alloc_kernel() {
    int i = blockIdx.x * blockDim.x + threadIdx.x;
    if (i < N_NODES) {
        int d = g_deg[i];
        int o = atomicAdd(&g_total, d);   // disjoint contiguous ranges
        g_off[i] = o;
        g_cursor[i] = o;
        g_dinv[i] = rsqrtf((float)d + 1.0f);  // +1 = self loop
    }
}

__global__ void fill_kernel(const int* __restrict__ ei) {
    int e = blockIdx.x * blockDim.x + threadIdx.x;
    if (e < N_EDGES) {
        int s = __ldcs(ei + e);
        int d = __ldcs(ei + N_EDGES + e);
        int pos = atomicAdd(&g_cursor[d], 1);
        float nm = g_dinv[s] * g_dinv[d];   // dinv ready (fill after alloc)
        g_csr[pos] = make_int2(s, __float_as_int(nm));
    }
}

// ---------------------------------------------------------------------------
// GEMM: g_xw = fp16(onehot @ g_wh), fp16 mma m16n8k16 with fp32 accumulate.
// Launched twice (pass = column half) so aggregation can start after half 1.
// 256x128x32 block tile, 256 threads = 8 warps (4m x 2n), warp tile 64x64.
// ---------------------------------------------------------------------------
#define BM 256
#define BN 128
#define BK 32
#define SAH 40    // A smem row stride (halves)
#define SBH 136   // B smem row stride (halves)
#define A_BUF_H (BM * SAH)              // 10240 halves per buffer
#define B_BASE_H (2 * A_BUF_H)          // 20480
#define B_BUF_H (BK * SBH)              // 4352 halves per buffer
#define SMEM_DYN ((B_BASE_H + 2 * B_BUF_H) * 2)  // 58368 bytes

__device__ __forceinline__ unsigned smem_u32(const void* p) {
    return (unsigned)__cvta_generic_to_shared(p);
}

__device__ __forceinline__ void ldsm_x4(unsigned* r, const void* p) {
    asm volatile("ldmatrix.sync.aligned.m8n8.x4.shared.b16 {%0,%1,%2,%3}, [%4];"
                 : "=r"(r[0]), "=r"(r[1]), "=r"(r[2]), "=r"(r[3]) : "r"(smem_u32(p)));
}

__device__ __forceinline__ void ldsm_x4_trans(unsigned* r, const void* p) {
    asm volatile("ldmatrix.sync.aligned.m8n8.x4.trans.shared.b16 {%0,%1,%2,%3}, [%4];"
                 : "=r"(r[0]), "=r"(r[1]), "=r"(r[2]), "=r"(r[3]) : "r"(smem_u32(p)));
}

__device__ __forceinline__ void mma_f16(float* c, const unsigned* a, const unsigned* b) {
    asm volatile(
        "mma.sync.aligned.m16n8k16.row.col.f32.f16.f16.f32 "
        "{%0,%1,%2,%3}, {%4,%5,%6,%7}, {%8,%9}, {%0,%1,%2,%3};"
        : "+f"(c[0]), "+f"(c[1]), "+f"(c[2]), "+f"(c[3])
        : "r"(a[0]), "r"(a[1]), "r"(a[2]), "r"(a[3]), "r"(b[0]), "r"(b[1]));
}

__global__ __launch_bounds__(256, 1) void gemm_kernel(const float* __restrict__ A, int pass) {
    extern __shared__ __half sm[];

    const int tid = threadIdx.x;
    const int rowBase = blockIdx.y * BM;
    const int colBase = (blockIdx.x + 2 * pass) * BN;

    const int arow = tid >> 2;            // 0..63 (+64*i)
    const int akc  = (tid & 3) * 8;       // 0,8,16,24
    const int bk   = tid >> 4;            // 0..15 (+16*j)
    const int bn   = (tid & 15) * 8;      // 0..120

    const float*  Aptr = A + (size_t)(rowBase + arow) * N_FEAT + akc;
    const __half* Bptr = g_wh + (size_t)bk * N_FEAT + colBase + bn;

    bool aok[4];
#pragma unroll
    for (int i = 0; i < 4; i++) aok[i] = (rowBase + arow + 64 * i) < N_NODES;

    const int warpId = tid >> 5;
    const int lane = tid & 31;
    const int wm = (warpId >> 1) * 64;    // 0,64,128,192
    const int wn = (warpId & 1) * 64;     // 0,64
    const int lr = lane & 15;             // ldmatrix row
    const int lc = (lane >> 4) * 8;       // ldmatrix col block
    const int qr = lane >> 2;             // mma c row
    const int qc = lane & 3;              // mma c col pair

    float acc[4][8][4] = {};              // [mi][ni][reg]

    float4 aR[4][2];
    uint4 bR[2];
#pragma unroll
    for (int i = 0; i < 4; i++) {
        if (aok[i]) {
            aR[i][0] = __ldcs(reinterpret_cast<const float4*>(Aptr + (size_t)64 * i * N_FEAT));
            aR[i][1] = __ldcs(reinterpret_cast<const float4*>(Aptr + (size_t)64 * i * N_FEAT + 4));
        } else {
            aR[i][0] = aR[i][1] = make_float4(0.f, 0.f, 0.f, 0.f);
        }
    }
#pragma unroll
    for (int j = 0; j < 2; j++)
        bR[j] = *reinterpret_cast<const uint4*>(Bptr + (size_t)16 * j * N_FEAT);

    int buf = 0;
    for (int kb = 0; kb < N_FEAT; kb += BK) {
#pragma unroll
        for (int i = 0; i < 4; i++)
            *reinterpret_cast<uint4*>(&sm[buf * A_BUF_H + (arow + 64 * i) * SAH + akc]) =
                cvt8(aR[i][0], aR[i][1]);
#pragma unroll
        for (int j = 0; j < 2; j++)
            *reinterpret_cast<uint4*>(&sm[B_BASE_H + buf * B_BUF_H + (bk + 16 * j) * SBH + bn]) = bR[j];
        __syncthreads();

        if (kb + BK < N_FEAT) {
#pragma unroll
            for (int i = 0; i < 4; i++)
                if (aok[i]) {
                    aR[i][0] = __ldcs(reinterpret_cast<const float4*>(
                        Aptr + (size_t)64 * i * N_FEAT + kb + BK));
                    aR[i][1] = __ldcs(reinterpret_cast<const float4*>(
                        Aptr + (size_t)64 * i * N_FEAT + kb + BK + 4));
                }
#pragma unroll
            for (int j = 0; j < 2; j++)
                bR[j] = *reinterpret_cast<const uint4*>(
                    Bptr + (size_t)(kb + BK + 16 * j) * N_FEAT);
        }

#pragma unroll
        for (int ks = 0; ks < 2; ks++) {
            const int k0 = ks * 16;
            unsigned af[4][4];
#pragma unroll
            for (int mi = 0; mi < 4; mi++)
                ldsm_x4(af[mi], &sm[buf * A_BUF_H + (wm + mi * 16 + lr) * SAH + k0 + lc]);
            unsigned bf[4][4];
#pragma unroll
            for (int nj = 0; nj < 4; nj++)
                ldsm_x4_trans(bf[nj], &sm[B_BASE_H + buf * B_BUF_H + (k0 + lr) * SBH + wn + nj * 16 + lc]);
#pragma unroll
            for (int mi = 0; mi < 4; mi++)
#pragma unroll
                for (int ni = 0; ni < 8; ni++)
                    mma_f16(acc[mi][ni], af[mi], &bf[ni >> 1][(ni & 1) * 2]);
        }
        __syncthreads();
        buf ^= 1;
    }

#pragma unroll
    for (int mi = 0; mi < 4; mi++) {
        const int r0 = rowBase + wm + mi * 16 + qr;
        const int r1 = r0 + 8;
#pragma unroll
        for (int ni = 0; ni < 8; ni++) {
            const int col = colBase + wn + ni * 8 + 2 * qc;
            if (r0 < N_NODES) {
                __half2 h = __floats2half2_rn(acc[mi][ni][0], acc[mi][ni][1]);
                *reinterpret_cast<__half2*>(&g_xw[(size_t)r0 * N_FEAT + col]) = h;
            }
            if (r1 < N_NODES) {
                __half2 h = __floats2half2_rn(acc[mi][ni][2], acc[mi][ni][3]);
                *reinterpret_cast<__half2*>(&g_xw[(size_t)r1 * N_FEAT + col]) = h;
            }
        }
    }
}

// ---------------------------------------------------------------------------
// Aggregate helpers. One warp per node, lane owns one uint4 (8 halves) of the
// 256-feature column half being processed. Nodes assigned by work-stealing.
// ---------------------------------------------------------------------------
__device__ __forceinline__ void acc_half8(float4& a0, float4& a1, uint4 raw, float m) {
    __half2 h0 = *reinterpret_cast<__half2*>(&raw.x);
    __half2 h1 = *reinterpret_cast<__half2*>(&raw.y);
    __half2 h2 = *reinterpret_cast<__half2*>(&raw.z);
    __half2 h3 = *reinterpret_cast<__half2*>(&raw.w);
    float2 f0 = __half22float2(h0);
    float2 f1 = __half22float2(h1);
    float2 f2 = __half22float2(h2);
    float2 f3 = __half22float2(h3);
    a0.x = fmaf(f0.x, m, a0.x); a0.y = fmaf(f0.y, m, a0.y);
    a0.z = fmaf(f1.x, m, a0.z); a0.w = fmaf(f1.y, m, a0.w);
    a1.x = fmaf(f2.x, m, a1.x); a1.y = fmaf(f2.y, m, a1.y);
    a1.z = fmaf(f3.x, m, a1.z); a1.w = fmaf(f3.y, m, a1.w);
}

// Gathers one column half for node n into (A0, A1), adds bias, applies relu.
__device__ __forceinline__ void gather_half(int n, int chunk, float4& A0, float4& A1,
                                            const float* __restrict__ bias) {
    const float dn = g_dinv[n];
    const uint4* __restrict__ xw4 = reinterpret_cast<const uint4*>(g_xw);

    A0 = make_float4(0.f, 0.f, 0.f, 0.f); A1 = A0;
    acc_half8(A0, A1, __ldcg(xw4 + (size_t)n * NCH16 + chunk), dn * dn);   // self loop

    const int start = g_off[n];
    const int cnt = g_deg[n];
    const int2* __restrict__ lst = g_csr + start;

    int i = 0;
    for (; i + 8 <= cnt; i += 8) {
        int2 e0 = __ldcs(lst + i),     e1 = __ldcs(lst + i + 1);
        int2 e2 = __ldcs(lst + i + 2), e3 = __ldcs(lst + i + 3);
        int2 e4 = __ldcs(lst + i + 4), e5 = __ldcs(lst + i + 5);
        int2 e6 = __ldcs(lst + i + 6), e7 = __ldcs(lst + i + 7);
        uint4 v0 = __ldcg(xw4 + (size_t)e0.x * NCH16 + chunk);
        uint4 v1 = __ldcg(xw4 + (size_t)e1.x * NCH16 + chunk);
        uint4 v2 = __ldcg(xw4 + (size_t)e2.x * NCH16 + chunk);
        uint4 v3 = __ldcg(xw4 + (size_t)e3.x * NCH16 + chunk);
        uint4 v4 = __ldcg(xw4 + (size_t)e4.x * NCH16 + chunk);
        uint4 v5 = __ldcg(xw4 + (size_t)e5.x * NCH16 + chunk);
        uint4 v6 = __ldcg(xw4 + (size_t)e6.x * NCH16 + chunk);
        uint4 v7 = __ldcg(xw4 + (size_t)e7.x * NCH16 + chunk);
        acc_half8(A0, A1, v0, __int_as_float(e0.y));
        acc_half8(A0, A1, v1, __int_as_float(e1.y));
        acc_half8(A0, A1, v2, __int_as_float(e2.y));
        acc_half8(A0, A1, v3, __int_as_float(e3.y));
        acc_half8(A0, A1, v4, __int_as_float(e4.y));
        acc_half8(A0, A1, v5, __int_as_float(e5.y));
        acc_half8(A0, A1, v6, __int_as_float(e6.y));
        acc_half8(A0, A1, v7, __int_as_float(e7.y));
    }
    for (; i < cnt; i++) {
        int2 e = __ldcs(lst + i);
        acc_half8(A0, A1, __ldcg(xw4 + (size_t)e.x * NCH16 + chunk), __int_as_float(e.y));
    }

    const float4* b4 = reinterpret_cast<const float4*>(bias);
    float4 ba0 = b4[2 * chunk], ba1 = b4[2 * chunk + 1];
    A0.x = fmaxf(A0.x + ba0.x, 0.f); A0.y = fmaxf(A0.y + ba0.y, 0.f);
    A0.z = fmaxf(A0.z + ba0.z, 0.f); A0.w = fmaxf(A0.w + ba0.w, 0.f);
    A1.x = fmaxf(A1.x + ba1.x, 0.f); A1.y = fmaxf(A1.y + ba1.y, 0.f);
    A1.z = fmaxf(A1.z + ba1.z, 0.f); A1.w = fmaxf(A1.w + ba1.w, 0.f);
}

// Half 0: write relu'd logits to fp16 staging buffer g_l0. Work-stealing.
__global__ __launch_bounds__(256) void aggregate_half0_kernel(const float* __restrict__ bias) {
    const int lane = threadIdx.x & 31;
    for (;;) {
        int n;
        if (lane == 0) n = atomicAdd(&g_ctr0, 1);
        n = __shfl_sync(0xFFFFFFFF, n, 0);
        if (n >= N_NODES) return;

        float4 A0, A1;
        gather_half(n, lane, A0, A1, bias);
        __half2 h0 = __floats2half2_rn(A0.x, A0.y);
        __half2 h1 = __floats2half2_rn(A0.z, A0.w);
        __half2 h2 = __floats2half2_rn(A1.x, A1.y);
        __half2 h3 = __floats2half2_rn(A1.z, A1.w);
        uint4 v;
        v.x = *reinterpret_cast<unsigned*>(&h0);
        v.y = *reinterpret_cast<unsigned*>(&h1);
        v.z = *reinterpret_cast<unsigned*>(&h2);
        v.w = *reinterpret_cast<unsigned*>(&h3);
        __stcs(reinterpret_cast<uint4*>(g_l0) + (size_t)n * 32 + lane, v);
    }
}

// Half 1 + fused softmax: gather columns 256..511, read fp16 half-0 logits,
// normalize the full row, and write the fp32 output once. Work-stealing.
__global__ __launch_bounds__(256) void aggregate_half1_final_kernel(const float* __restrict__ bias,
                                                                    float* __restrict__ out) {
    const int lane = threadIdx.x & 31;
    for (;;) {
        int n;
        if (lane == 0) n = atomicAdd(&g_ctr1, 1);
        n = __shfl_sync(0xFFFFFFFF, n, 0);
        if (n >= N_NODES) return;

        float4 A0, A1;
        gather_half(n, 32 + lane, A0, A1, bias);

        uint4 raw = __ldcg(reinterpret_cast<const uint4*>(g_l0) + (size_t)n * 32 + lane);
        __half2 h0 = *reinterpret_cast<__half2*>(&raw.x);
        __half2 h1 = *reinterpret_cast<__half2*>(&raw.y);
        __half2 h2 = *reinterpret_cast<__half2*>(&raw.z);
        __half2 h3 = *reinterpret_cast<__half2*>(&raw.w);
        float2 f0 = __half22float2(h0), f1 = __half22float2(h1);
        float2 f2 = __half22float2(h2), f3 = __half22float2(h3);
        float4 L0 = make_float4(f0.x, f0.y, f1.x, f1.y);
        float4 L1 = make_float4(f2.x, f2.y, f3.x, f3.y);

        float m = fmaxf(fmaxf(fmaxf(A0.x, A0.y), fmaxf(A0.z, A0.w)),
                        fmaxf(fmaxf(A1.x, A1.y), fmaxf(A1.z, A1.w)));
        m = fmaxf(m, fmaxf(fmaxf(fmaxf(L0.x, L0.y), fmaxf(L0.z, L0.w)),
                           fmaxf(fmaxf(L1.x, L1.y), fmaxf(L1.z, L1.w))));
#pragma unroll
        for (int o = 16; o > 0; o >>= 1)
            m = fmaxf(m, __shfl_xor_sync(0xFFFFFFFF, m, o));

        A0.x = __expf(A0.x - m); A0.y = __expf(A0.y - m);
        A0.z = __expf(A0.z - m); A0.w = __expf(A0.w - m);
        A1.x = __expf(A1.x - m); A1.y = __expf(A1.y - m);
        A1.z = __expf(A1.z - m); A1.w = __expf(A1.w - m);
        L0.x = __expf(L0.x - m); L0.y = __expf(L0.y - m);
        L0.z = __expf(L0.z - m); L0.w = __expf(L0.w - m);
        L1.x = __expf(L1.x - m); L1.y = __expf(L1.y - m);
        L1.z = __expf(L1.z - m); L1.w = __expf(L1.w - m);

        float s = A0.x + A0.y + A0.z + A0.w + A1.x + A1.y + A1.z + A1.w +
                  L0.x + L0.y + L0.z + L0.w + L1.x + L1.y + L1.z + L1.w;
#pragma unroll
        for (int o = 16; o > 0; o >>= 1)
            s += __shfl_xor_sync(0xFFFFFFFF, s, o);

        float inv = __frcp_rn(s);
        A0.x *= inv; A0.y *= inv; A0.z *= inv; A0.w *= inv;
        A1.x *= inv; A1.y *= inv; A1.z *= inv; A1.w *= inv;
        L0.x *= inv; L0.y *= inv; L0.z *= inv; L0.w *= inv;
        L1.x *= inv; L1.y *= inv; L1.z *= inv; L1.w *= inv;

        float4* orow = reinterpret_cast<float4*>(out) + (size_t)n * (N_FEAT / 4);
        __stcs(orow + 2 * lane,              L0);
        __stcs(orow + 2 * lane + 1,          L1);
        __stcs(orow + 2 * (32 + lane),       A0);
        __stcs(orow + 2 * (32 + lane) + 1,   A1);
    }
}

// ---------------------------------------------------------------------------
// Launch graph:
//   main: cvtW -> gemmA(evA) -> gemmB(evB)
//   side: zero -> count -> alloc -> fill -> [wait evA] agg0 -> [wait evB]
//         agg1+softmax -> (join main)
// gemmA is the 4th submitted launch (ncu slot).
// ---------------------------------------------------------------------------
extern "C" void kernel_launch(void* const* d_in, const int* in_sizes, int n_in,
                              void* d_out, int out_size) {
    const float* onehot = (const float*)d_in[0];
    const int*   ei     = (const int*)d_in[1];    // [2, E]: src then dst
    const float* W      = (const float*)d_in[2];
    const float* b      = (const float*)d_in[3];
    float* out = (float*)d_out;

    static cudaStream_t side = nullptr;
    static cudaEvent_t evFork = nullptr, evA = nullptr, evB = nullptr, evJoin = nullptr;
    if (!side) {
        cudaStreamCreateWithFlags(&side, cudaStreamNonBlocking);
        cudaEventCreateWithFlags(&evFork, cudaEventDisableTiming);
        cudaEventCreateWithFlags(&evA, cudaEventDisableTiming);
        cudaEventCreateWithFlags(&evB, cudaEventDisableTiming);
        cudaEventCreateWithFlags(&evJoin, cudaEventDisableTiming);
        cudaFuncSetAttribute(gemm_kernel, cudaFuncAttributeMaxDynamicSharedMemorySize, SMEM_DYN);
    }

    cudaEventRecord(evFork, 0);
    cudaStreamWaitEvent(side, evFork, 0);

    const int gy = (N_NODES + BM - 1) / BM;
    const int aggBlocks = 148 * 12;   // persistent-ish; stragglers steal leftovers

    cvtW_kernel<<<(N_FEAT * N_FEAT / 8 + 255) / 256, 256>>>(W);                   // #1
    zero_kernel<<<(N_NODES + 255) / 256, 256, 0, side>>>();                       // #2
    count_deg_kernel<<<(N_EDGES + 255) / 256, 256, 0, side>>>(ei + N_EDGES);      // #3
    gemm_kernel<<<dim3(2, gy), 256, SMEM_DYN>>>(onehot, 0);                       // #4 (ncu)
    cudaEventRecord(evA, 0);
    gemm_kernel<<<dim3(2, gy), 256, SMEM_DYN>>>(onehot, 1);
    cudaEventRecord(evB, 0);

    alloc_kernel<<<(N_NODES + 255) / 256, 256, 0, side>>>();
    fill_kernel<<<(N_EDGES + 255) / 256, 256, 0, side>>>(ei);

    cudaStreamWaitEvent(side, evA, 0);
    aggregate_half0_kernel<<<aggBlocks, 256, 0, side>>>(b);
    cudaStreamWaitEvent(side, evB, 0);
    aggregate_half1_final_kernel<<<aggBlocks, 256, 0, side>>>(b, out);

    cudaEventRecord(evJoin, side);
    cudaStreamWaitEvent(0, evJoin, 0);
}